// round 4
// baseline (speedup 1.0000x reference)
#include <cuda_runtime.h>
#include <math.h>

#define NN 4096
#define DD 256
#define CAPS 512    // candidate capacity (typical ~20-40 at tau0 = max-1)

// ---------------- device scratch ----------------
__device__ float g_negT[(size_t)NN * NN];   // -cost^T
__device__ float g_tau_col[NN];
__device__ float g_beta[(size_t)NN * DD];
__device__ float g_alpha[(size_t)NN * DD];
__device__ float g_v1[DD];
__device__ float g_v2[DD];
__device__ float g_y;

// ---------------- warp helpers ----------------
__device__ __forceinline__ float warpRedSum(float v) {
#pragma unroll
    for (int o = 16; o > 0; o >>= 1) v += __shfl_xor_sync(0xffffffffu, v, o);
    return v;
}
__device__ __forceinline__ float warpRedMax(float v) {
#pragma unroll
    for (int o = 16; o > 0; o >>= 1) v = fmaxf(v, __shfl_xor_sync(0xffffffffu, v, o));
    return v;
}

// exclusive scan of per-thread counts over 512 threads (16 warps)
__device__ __forceinline__ int blockScanExcl512(int cnt, int& total, int tid) {
    __shared__ int warp_tot[16];
    const unsigned mask = 0xffffffffu;
    int lane = tid & 31, w = tid >> 5;
    int incl = cnt;
#pragma unroll
    for (int o = 1; o < 32; o <<= 1) {
        int n = __shfl_up_sync(mask, incl, o);
        if (lane >= o) incl += n;
    }
    if (lane == 31) warp_tot[w] = incl;
    __syncthreads();
    if (w == 0) {
        int t = (lane < 16) ? warp_tot[lane] : 0;
#pragma unroll
        for (int o = 1; o < 16; o <<= 1) {
            int n = __shfl_up_sync(mask, t, o);
            if (lane >= o) t += n;
        }
        if (lane < 16) warp_tot[lane] = t;   // inclusive warp totals
    }
    __syncthreads();
    int warp_off = (w == 0) ? 0 : warp_tot[w - 1];
    total = warp_tot[15];
    __syncthreads();
    return warp_off + incl - cnt;
}

// ---------------- sparsemax core ----------------
// 512 threads, 8 row elements per thread in registers.
// 1) block max -> tau0 = max-1 (provably <= all Michelot iterates)
// 2) compact candidates {x > tau0} (~20-40) deterministically into shared
// 3) warp 0 finishes Michelot barrier-free on the tiny list
// 4) broadcast tau; write alignment row from registers; sparse mix with V.
template <bool NEG, bool WRITE_ALIGN>
__device__ __forceinline__ void spmax_core(const float* __restrict__ xrow,
                                           float* __restrict__ align_row,
                                           float* __restrict__ tau_store,
                                           const float* __restrict__ V,
                                           float* __restrict__ mix_out, int row) {
    __shared__ float redM[16];
    __shared__ float redS[16], redC[16];
    __shared__ float s_x[CAPS];
    __shared__ unsigned short s_j[CAPS];
    __shared__ float s_tau;
    int tid = threadIdx.x;        // 512
    int lane = tid & 31, w = tid >> 5;

    // coalesced load into 8 registers; running max
    float x[8];
    float vmax = -3.0e38f;
#pragma unroll
    for (int k = 0; k < 2; k++) {
        float4 v = *(const float4*)(xrow + tid * 4 + k * 2048);
        if (NEG) { v.x = -v.x; v.y = -v.y; v.z = -v.z; v.w = -v.w; }
        x[k * 4 + 0] = v.x; x[k * 4 + 1] = v.y;
        x[k * 4 + 2] = v.z; x[k * 4 + 3] = v.w;
        vmax = fmaxf(vmax, fmaxf(fmaxf(v.x, v.y), fmaxf(v.z, v.w)));
    }

    // block max (1 barrier)
    float m = warpRedMax(vmax);
    if (lane == 0) redM[w] = m;
    __syncthreads();
    float bm = redM[0];
#pragma unroll
    for (int i = 1; i < 16; i++) bm = fmaxf(bm, redM[i]);

    const float tau0 = bm - 1.0f;   // lower bound on tau*, and on all iterates

    // deterministic candidate compaction
    int cnt = 0;
#pragma unroll
    for (int s = 0; s < 8; s++)
        if (x[s] > tau0) cnt++;
    int nnz;
    int base = blockScanExcl512(cnt, nnz, tid);
    if (nnz <= CAPS) {
        int pos = base;
#pragma unroll
        for (int s = 0; s < 8; s++) {
            if (x[s] > tau0) {
                s_x[pos] = x[s];
                s_j[pos] = (unsigned short)(tid * 4 + (s >> 2) * 2048 + (s & 3));
                pos++;
            }
        }
    }
    __syncthreads();

    float tau;
    if (nnz <= CAPS) {
        // warp 0 finishes Michelot barrier-free on the candidate list
        if (w == 0) {
            float t = tau0;
            int kprev = -1;
            for (int it = 0; it < 48; ++it) {
                float ls = 0.f, lc = 0.f;
                for (int n = lane; n < nnz; n += 32) {
                    float v = s_x[n];
                    if (v > t) { ls += v; lc += 1.0f; }
                }
                ls = warpRedSum(ls);
                lc = warpRedSum(lc);
                int k = (int)lc;
                if (k == kprev) break;
                t = (ls - 1.0f) / lc;
                kprev = k;
            }
            if (lane == 0) s_tau = t;
        }
        __syncthreads();
        tau = s_tau;
    } else {
        // fallback: block-wide Michelot on registers (rare/never for this data)
        tau = tau0;
        int kprev = -1;
        for (int it = 0; it < 64; ++it) {
            float ls = 0.f, lc = 0.f;
#pragma unroll
            for (int s = 0; s < 8; s++) {
                float v = x[s];
                if (v > tau) { ls += v; lc += 1.0f; }
            }
            ls = warpRedSum(ls);
            lc = warpRedSum(lc);
            if (lane == 0) { redS[w] = ls; redC[w] = lc; }
            __syncthreads();
            float S = 0.f, K = 0.f;
#pragma unroll
            for (int i = 0; i < 16; i++) { S += redS[i]; K += redC[i]; }
            int k = (int)K;
            __syncthreads();
            if (k == kprev) break;
            tau = (S - 1.0f) / K;
            kprev = k;
        }
    }

    if (tau_store && tid == 0) *tau_store = tau;

    // alignment row straight from registers (coalesced)
    if (WRITE_ALIGN) {
#pragma unroll
        for (int k = 0; k < 2; k++) {
            float4 o;
            o.x = fmaxf(x[k * 4 + 0] - tau, 0.f);
            o.y = fmaxf(x[k * 4 + 1] - tau, 0.f);
            o.z = fmaxf(x[k * 4 + 2] - tau, 0.f);
            o.w = fmaxf(x[k * 4 + 3] - tau, 0.f);
            *(float4*)(align_row + tid * 4 + k * 2048) = o;
        }
    }

    // sparse mix: out[row, d] = sum_n max(x_n - tau, 0) * V[j_n, d]
    if (nnz <= CAPS) {
        if (tid < DD) {
            float acc = 0.f;
            for (int n = 0; n < nnz; n++) {
                float p = fmaxf(s_x[n] - tau, 0.f);   // non-support contributes 0
                acc = fmaf(p, V[(size_t)s_j[n] * DD + tid], acc);
            }
            mix_out[(size_t)row * DD + tid] = acc;
        }
    } else {
        if (tid < DD) {
            float acc = 0.f;
            for (int j = 0; j < NN; j++) {
                float xv = NEG ? -xrow[j] : xrow[j];
                float p = xv - tau;
                if (p > 0.f) acc = fmaf(p, V[(size_t)j * DD + tid], acc);
            }
            mix_out[(size_t)row * DD + tid] = acc;
        }
    }
}

// ---------------- kernels ----------------
__global__ void zero_kernel() {
    int t = threadIdx.x;
    g_v1[t] = 0.f;
    g_v2[t] = 0.f;
}

// float4 in both directions; 32x32 tile, 256 threads (8x32)
__global__ void transpose_neg_kernel(const float* __restrict__ in) {
    __shared__ float s[32][33];
    int bx = blockIdx.x * 32, by = blockIdx.y * 32;
    int tx = threadIdx.x;   // 0..7
    int ty = threadIdx.y;   // 0..31

    float4 v = *(const float4*)(in + (size_t)(by + ty) * NN + bx + tx * 4);
    s[ty][tx * 4 + 0] = -v.x;
    s[ty][tx * 4 + 1] = -v.y;
    s[ty][tx * 4 + 2] = -v.z;
    s[ty][tx * 4 + 3] = -v.w;
    __syncthreads();

    float4 o;
    o.x = s[tx * 4 + 0][ty];
    o.y = s[tx * 4 + 1][ty];
    o.z = s[tx * 4 + 2][ty];
    o.w = s[tx * 4 + 3][ty];
    *(float4*)(g_negT + (size_t)(bx + ty) * NN + by + tx * 4) = o;
}

__global__ __launch_bounds__(512) void spmax_row_kernel(const float* __restrict__ cost,
                                                        float* __restrict__ a0,
                                                        const float* __restrict__ colvecs) {
    int row = blockIdx.x;
    spmax_core<true, true>(cost + (size_t)row * NN, a0 + (size_t)row * NN, nullptr,
                           colvecs, g_beta, row);
}

__global__ __launch_bounds__(512) void spmax_col_kernel(const float* __restrict__ rowvecs) {
    int row = blockIdx.x;   // column index of the original cost matrix
    spmax_core<false, false>(g_negT + (size_t)row * NN, nullptr, &g_tau_col[row],
                             rowvecs, g_alpha, row);
}

// partial sums of leaky_relu(X @ W + b) over 16 rows per block; y-dim picks matrix
__global__ __launch_bounds__(256) void g_mean_kernel(const float* __restrict__ Wg,
                                                     const float* __restrict__ bg) {
    int which = blockIdx.y;
    const float* Xall = which ? g_alpha : g_beta;
    float* gv = which ? g_v2 : g_v1;
    __shared__ float xs[16 * 256];
    int tid = threadIdx.x;
    size_t r0 = (size_t)blockIdx.x * 16;
#pragma unroll
    for (int r = 0; r < 16; r++) xs[r * 256 + tid] = Xall[(r0 + r) * 256 + tid];
    __syncthreads();

    float acc[16];
#pragma unroll
    for (int r = 0; r < 16; r++) acc[r] = 0.f;
#pragma unroll 4
    for (int k = 0; k < 256; k++) {
        float w = Wg[k * 256 + tid];
#pragma unroll
        for (int r = 0; r < 16; r++) acc[r] = fmaf(xs[r * 256 + k], w, acc[r]);
    }
    float bb = bg[tid], s = 0.f;
#pragma unroll
    for (int r = 0; r < 16; r++) {
        float z = acc[r] + bb;
        s += (z > 0.f) ? z : 0.2f * z;
    }
    atomicAdd(&gv[tid], s);
}

__global__ void cosine_kernel() {
    __shared__ float red[24];
    int tid = threadIdx.x;
    float v1 = g_v1[tid] * (1.0f / NN);
    float v2 = g_v2[tid] * (1.0f / NN);
    float d = v1 * v2, a = v1 * v1, b = v2 * v2;
    d = warpRedSum(d); a = warpRedSum(a); b = warpRedSum(b);
    if ((tid & 31) == 0) {
        red[tid >> 5] = d; red[8 + (tid >> 5)] = a; red[16 + (tid >> 5)] = b;
    }
    __syncthreads();
    if (tid == 0) {
        float D = 0.f, A = 0.f, B = 0.f;
#pragma unroll
        for (int i = 0; i < 8; i++) { D += red[i]; A += red[8 + i]; B += red[16 + i]; }
        g_y = 1.0f - D / (sqrtf(A) * sqrtf(B) + 1e-8f);
    }
}

// fused: a1[i,j] = max(-cost[i,j] - tau_col[j], 0)  AND  cost_out = y
__global__ void tail_kernel(const float* __restrict__ cost,
                            float* __restrict__ a1, float* __restrict__ cost_out) {
    size_t idx = ((size_t)blockIdx.x * blockDim.x + threadIdx.x) * 4;
    int j = (int)(idx & (NN - 1));
    float4 c = *(const float4*)(cost + idx);
    float4 o;
    o.x = fmaxf(-c.x - g_tau_col[j + 0], 0.f);
    o.y = fmaxf(-c.y - g_tau_col[j + 1], 0.f);
    o.z = fmaxf(-c.z - g_tau_col[j + 2], 0.f);
    o.w = fmaxf(-c.w - g_tau_col[j + 3], 0.f);
    *(float4*)(a1 + idx) = o;
    float y = g_y;
    *(float4*)(cost_out + idx) = make_float4(y, y, y, y);
}

// ---------------- launch ----------------
extern "C" void kernel_launch(void* const* d_in, const int* in_sizes, int n_in,
                              void* d_out, int out_size) {
    const float* row_vecs    = (const float*)d_in[0];
    const float* column_vecs = (const float*)d_in[1];
    const float* cost        = (const float*)d_in[2];
    const float* W_G         = (const float*)d_in[3];
    const float* b_G         = (const float*)d_in[4];

    float* out      = (float*)d_out;
    float* cost_out = out;
    float* a0       = out + (size_t)NN * NN;
    float* a1       = out + 2 * (size_t)NN * NN;

    (void)in_sizes; (void)n_in; (void)out_size;

    zero_kernel<<<1, 256>>>();
    transpose_neg_kernel<<<dim3(NN / 32, NN / 32), dim3(8, 32)>>>(cost);
    spmax_row_kernel<<<NN, 512>>>(cost, a0, column_vecs);
    spmax_col_kernel<<<NN, 512>>>(row_vecs);
    g_mean_kernel<<<dim3(NN / 16, 2), 256>>>(W_G, b_G);
    cosine_kernel<<<1, 256>>>();
    tail_kernel<<<(NN * (size_t)NN) / (4 * 256), 256>>>(cost, a1, cost_out);
}

// round 5
// speedup vs baseline: 1.0309x; 1.0309x over previous
#include <cuda_runtime.h>
#include <math.h>

#define NN 4096
#define DD 256
#define CAPS 1024   // support/candidate capacity (expected nnz ~ 5-10)

// ---------------- device scratch ----------------
__device__ float g_negT[(size_t)NN * NN];   // -cost^T
__device__ float g_tau_col[NN];
__device__ float g_beta[(size_t)NN * DD];
__device__ float g_alpha[(size_t)NN * DD];
__device__ float g_v1[DD];
__device__ float g_v2[DD];
__device__ float g_y;

// ---------------- warp helpers ----------------
__device__ __forceinline__ float warpRedSum(float v) {
#pragma unroll
    for (int o = 16; o > 0; o >>= 1) v += __shfl_xor_sync(0xffffffffu, v, o);
    return v;
}
__device__ __forceinline__ float warpRedMax(float v) {
#pragma unroll
    for (int o = 16; o > 0; o >>= 1) v = fmaxf(v, __shfl_xor_sync(0xffffffffu, v, o));
    return v;
}

// exclusive scan of per-thread counts over 256 threads
__device__ __forceinline__ int blockScanExcl(int cnt, int& total, int tid) {
    __shared__ int warp_tot[8];
    const unsigned mask = 0xffffffffu;
    int lane = tid & 31, w = tid >> 5;
    int incl = cnt;
#pragma unroll
    for (int o = 1; o < 32; o <<= 1) {
        int n = __shfl_up_sync(mask, incl, o);
        if (lane >= o) incl += n;
    }
    if (lane == 31) warp_tot[w] = incl;
    __syncthreads();
    if (w == 0) {
        int t = (lane < 8) ? warp_tot[lane] : 0;
#pragma unroll
        for (int o = 1; o < 8; o <<= 1) {
            int n = __shfl_up_sync(mask, t, o);
            if (lane >= o) t += n;
        }
        if (lane < 8) warp_tot[lane] = t;
    }
    __syncthreads();
    int warp_off = (w == 0) ? 0 : warp_tot[w - 1];
    total = warp_tot[7];
    __syncthreads();
    return warp_off + incl - cnt;
}

// ---------------- register-resident sparsemax core (round-3 structure) ----------------
// 256 threads, 16 row elements per thread in registers.
// tau0 = max-1 (valid Michelot start), block-wide iterations w/ 1 barrier each.
// WRITE_A1: also emit a1[row, j] = max(x_j - tau_col[j], 0) (row kernel only).
template <bool NEG, bool WRITE_ALIGN, bool WRITE_A1>
__device__ __forceinline__ void spmax_core(const float* __restrict__ xrow,
                                           float* __restrict__ align_row,
                                           float* __restrict__ a1_row,
                                           const float* __restrict__ tau_col,
                                           float* __restrict__ tau_store,
                                           const float* __restrict__ V,
                                           float* __restrict__ mix_out, int row) {
    __shared__ float red[8 + 64];     // [0..7] max partials; [8..] (sum,count) x 2 parities
    __shared__ float s_p[CAPS];
    __shared__ unsigned short s_j[CAPS];
    int tid = threadIdx.x;   // 256

    // coalesced load into registers; running max
    float x[16];
    float vmax = -3.0e38f;
#pragma unroll
    for (int k = 0; k < 4; k++) {
        float4 v = *(const float4*)(xrow + tid * 4 + k * 1024);
        if (NEG) { v.x = -v.x; v.y = -v.y; v.z = -v.z; v.w = -v.w; }
        x[k * 4 + 0] = v.x; x[k * 4 + 1] = v.y;
        x[k * 4 + 2] = v.z; x[k * 4 + 3] = v.w;
        vmax = fmaxf(vmax, fmaxf(fmaxf(v.x, v.y), fmaxf(v.z, v.w)));
    }

    // block max (1 barrier)
    float m = warpRedMax(vmax);
    if ((tid & 31) == 0) red[tid >> 5] = m;
    __syncthreads();
    float bm = red[0];
#pragma unroll
    for (int i = 1; i < 8; i++) bm = fmaxf(bm, red[i]);

    float tau = bm - 1.0f;     // tau0 <= tau* -> support superset, Michelot valid
    int kprev = -1;

    for (int it = 0; it < 64; ++it) {
        float ls = 0.f, lc = 0.f;
#pragma unroll
        for (int s = 0; s < 16; s++) {
            float v = x[s];
            if (v > tau) { ls += v; lc += 1.0f; }
        }
        ls = warpRedSum(ls);
        lc = warpRedSum(lc);
        int p = it & 1;
        float* buf = red + 8 + p * 32;
        if ((tid & 31) == 0) { buf[tid >> 5] = ls; buf[8 + (tid >> 5)] = lc; }
        __syncthreads();
        float S = 0.f, K = 0.f;
#pragma unroll
        for (int i = 0; i < 8; i++) { S += buf[i]; K += buf[8 + i]; }
        int k = (int)K;
        if (k == kprev) break;           // uniform across block
        tau = (S - 1.0f) / K;
        kprev = k;
    }

    if (tau_store && tid == 0) *tau_store = tau;

    // alignment rows straight from registers (coalesced streaming stores)
    if (WRITE_ALIGN) {
#pragma unroll
        for (int k = 0; k < 4; k++) {
            int j = tid * 4 + k * 1024;
            float4 o;
            o.x = fmaxf(x[k * 4 + 0] - tau, 0.f);
            o.y = fmaxf(x[k * 4 + 1] - tau, 0.f);
            o.z = fmaxf(x[k * 4 + 2] - tau, 0.f);
            o.w = fmaxf(x[k * 4 + 3] - tau, 0.f);
            __stcs((float4*)(align_row + j), o);
            if (WRITE_A1) {
                const float4 tc = *(const float4*)(tau_col + j);
                float4 o1;
                o1.x = fmaxf(x[k * 4 + 0] - tc.x, 0.f);
                o1.y = fmaxf(x[k * 4 + 1] - tc.y, 0.f);
                o1.z = fmaxf(x[k * 4 + 2] - tc.z, 0.f);
                o1.w = fmaxf(x[k * 4 + 3] - tc.w, 0.f);
                __stcs((float4*)(a1_row + j), o1);
            }
        }
    }

    // deterministic support compaction
    int cnt = 0;
#pragma unroll
    for (int s = 0; s < 16; s++)
        if (x[s] > tau) cnt++;
    int nnz;
    int base = blockScanExcl(cnt, nnz, tid);
    if (nnz <= CAPS) {
        int pos = base;
#pragma unroll
        for (int s = 0; s < 16; s++) {
            if (x[s] > tau) {
                s_p[pos] = x[s] - tau;
                s_j[pos] = (unsigned short)(tid * 4 + (s >> 2) * 1024 + (s & 3));
                pos++;
            }
        }
    }
    __syncthreads();

    // mix: out[row, d] = sum_n p_n * V[j_n, d], d = tid (V rows L2-hot)
    float acc = 0.f;
    if (nnz <= CAPS) {
#pragma unroll 4
        for (int n = 0; n < nnz; n++)
            acc = fmaf(s_p[n], V[(size_t)s_j[n] * DD + tid], acc);
    } else {
        for (int j = 0; j < NN; j++) {
            float xv = NEG ? -xrow[j] : xrow[j];
            float p = xv - tau;
            if (p > 0.f) acc = fmaf(p, V[(size_t)j * DD + tid], acc);
        }
    }
    mix_out[(size_t)row * DD + tid] = acc;
}

// ---------------- kernels ----------------
__global__ void zero_kernel() {
    int t = threadIdx.x;
    g_v1[t] = 0.f;
    g_v2[t] = 0.f;
}

// float4 both directions; 32x32 tile, 256 threads (8x32)
__global__ void transpose_neg_kernel(const float* __restrict__ in) {
    __shared__ float s[32][33];
    int bx = blockIdx.x * 32, by = blockIdx.y * 32;
    int tx = threadIdx.x;   // 0..7
    int ty = threadIdx.y;   // 0..31

    float4 v = *(const float4*)(in + (size_t)(by + ty) * NN + bx + tx * 4);
    s[ty][tx * 4 + 0] = -v.x;
    s[ty][tx * 4 + 1] = -v.y;
    s[ty][tx * 4 + 2] = -v.z;
    s[ty][tx * 4 + 3] = -v.w;
    __syncthreads();

    float4 o;
    o.x = s[tx * 4 + 0][ty];
    o.y = s[tx * 4 + 1][ty];
    o.z = s[tx * 4 + 2][ty];
    o.w = s[tx * 4 + 3][ty];
    *(float4*)(g_negT + (size_t)(bx + ty) * NN + by + tx * 4) = o;
}

__global__ __launch_bounds__(256) void spmax_col_kernel(const float* __restrict__ rowvecs) {
    int row = blockIdx.x;   // column index of the original cost matrix
    spmax_core<false, false, false>(g_negT + (size_t)row * NN, nullptr, nullptr, nullptr,
                                    &g_tau_col[row], rowvecs, g_alpha, row);
}

// writes a0 AND a1 (uses tau_col, so runs after spmax_col)
__global__ __launch_bounds__(256) void spmax_row_kernel(const float* __restrict__ cost,
                                                        float* __restrict__ a0,
                                                        float* __restrict__ a1,
                                                        const float* __restrict__ colvecs) {
    int row = blockIdx.x;
    spmax_core<true, true, true>(cost + (size_t)row * NN, a0 + (size_t)row * NN,
                                 a1 + (size_t)row * NN, g_tau_col, nullptr,
                                 colvecs, g_beta, row);
}

// partial sums of leaky_relu(X @ W + b) over 16 rows per block
__global__ __launch_bounds__(256) void g_mean_kernel(const float* __restrict__ Wg,
                                                     const float* __restrict__ bg,
                                                     int which) {
    const float* Xall = which ? g_alpha : g_beta;
    float* gv = which ? g_v2 : g_v1;
    __shared__ float xs[16 * 256];
    int tid = threadIdx.x;
    size_t r0 = (size_t)blockIdx.x * 16;
#pragma unroll
    for (int r = 0; r < 16; r++) xs[r * 256 + tid] = Xall[(r0 + r) * 256 + tid];
    __syncthreads();

    float acc[16];
#pragma unroll
    for (int r = 0; r < 16; r++) acc[r] = 0.f;
#pragma unroll 4
    for (int k = 0; k < 256; k++) {
        float w = Wg[k * 256 + tid];
#pragma unroll
        for (int r = 0; r < 16; r++) acc[r] = fmaf(xs[r * 256 + k], w, acc[r]);
    }
    float bb = bg[tid], s = 0.f;
#pragma unroll
    for (int r = 0; r < 16; r++) {
        float z = acc[r] + bb;
        s += (z > 0.f) ? z : 0.2f * z;
    }
    atomicAdd(&gv[tid], s);
}

__global__ void cosine_kernel() {
    __shared__ float red[24];
    int tid = threadIdx.x;
    float v1 = g_v1[tid] * (1.0f / NN);
    float v2 = g_v2[tid] * (1.0f / NN);
    float d = v1 * v2, a = v1 * v1, b = v2 * v2;
    d = warpRedSum(d); a = warpRedSum(a); b = warpRedSum(b);
    if ((tid & 31) == 0) {
        red[tid >> 5] = d; red[8 + (tid >> 5)] = a; red[16 + (tid >> 5)] = b;
    }
    __syncthreads();
    if (tid == 0) {
        float D = 0.f, A = 0.f, B = 0.f;
#pragma unroll
        for (int i = 0; i < 8; i++) { D += red[i]; A += red[8 + i]; B += red[16 + i]; }
        g_y = 1.0f - D / (sqrtf(A) * sqrtf(B) + 1e-8f);
    }
}

__global__ void fill_kernel(float* __restrict__ out) {
    float y = g_y;
    size_t idx = ((size_t)blockIdx.x * blockDim.x + threadIdx.x) * 4;
    __stcs((float4*)(out + idx), make_float4(y, y, y, y));
}

// ---------------- launch ----------------
extern "C" void kernel_launch(void* const* d_in, const int* in_sizes, int n_in,
                              void* d_out, int out_size) {
    const float* row_vecs    = (const float*)d_in[0];
    const float* column_vecs = (const float*)d_in[1];
    const float* cost        = (const float*)d_in[2];
    const float* W_G         = (const float*)d_in[3];
    const float* b_G         = (const float*)d_in[4];

    float* out      = (float*)d_out;
    float* cost_out = out;
    float* a0       = out + (size_t)NN * NN;
    float* a1       = out + 2 * (size_t)NN * NN;

    (void)in_sizes; (void)n_in; (void)out_size;

    zero_kernel<<<1, 256>>>();
    transpose_neg_kernel<<<dim3(NN / 32, NN / 32), dim3(8, 32)>>>(cost);
    spmax_col_kernel<<<NN, 256>>>(row_vecs);                  // tau_col + alpha
    g_mean_kernel<<<NN / 16, 256>>>(W_G, b_G, 1);             // v2 from alpha
    spmax_row_kernel<<<NN, 256>>>(cost, a0, a1, column_vecs); // a0, a1, beta
    g_mean_kernel<<<NN / 16, 256>>>(W_G, b_G, 0);             // v1 from beta
    cosine_kernel<<<1, 256>>>();
    fill_kernel<<<(NN * (size_t)NN) / (4 * 256), 256>>>(cost_out);
}

// round 6
// speedup vs baseline: 1.2017x; 1.1657x over previous
#include <cuda_runtime.h>
#include <math.h>

#define NN 4096
#define DD 256
#define CAPS 1024   // support/candidate capacity (expected nnz ~ 5-10)

// ---------------- device scratch ----------------
__device__ float g_negT[(size_t)NN * NN];   // -cost^T
__device__ float g_tau_col[NN];
__device__ float g_beta[(size_t)NN * DD];
__device__ float g_alpha[(size_t)NN * DD];
__device__ float g_v1[DD];
__device__ float g_v2[DD];
__device__ float g_y;

// ---------------- warp helpers ----------------
__device__ __forceinline__ float warpRedSum(float v) {
#pragma unroll
    for (int o = 16; o > 0; o >>= 1) v += __shfl_xor_sync(0xffffffffu, v, o);
    return v;
}
__device__ __forceinline__ float warpRedMax(float v) {
#pragma unroll
    for (int o = 16; o > 0; o >>= 1) v = fmaxf(v, __shfl_xor_sync(0xffffffffu, v, o));
    return v;
}

// exclusive scan of per-thread counts over 256 threads
__device__ __forceinline__ int blockScanExcl(int cnt, int& total, int tid) {
    __shared__ int warp_tot[8];
    const unsigned mask = 0xffffffffu;
    int lane = tid & 31, w = tid >> 5;
    int incl = cnt;
#pragma unroll
    for (int o = 1; o < 32; o <<= 1) {
        int n = __shfl_up_sync(mask, incl, o);
        if (lane >= o) incl += n;
    }
    if (lane == 31) warp_tot[w] = incl;
    __syncthreads();
    if (w == 0) {
        int t = (lane < 8) ? warp_tot[lane] : 0;
#pragma unroll
        for (int o = 1; o < 8; o <<= 1) {
            int n = __shfl_up_sync(mask, t, o);
            if (lane >= o) t += n;
        }
        if (lane < 8) warp_tot[lane] = t;
    }
    __syncthreads();
    int warp_off = (w == 0) ? 0 : warp_tot[w - 1];
    total = warp_tot[7];
    __syncthreads();
    return warp_off + incl - cnt;
}

// ---------------- register-resident sparsemax core ----------------
// 256 threads, 16 row elements per thread in registers.
// tau0 = max-1 (valid Michelot start), block-wide iterations w/ 1 barrier each.
// WRITE_A1: also emit a1[row, j] = max(x_j - tau_col[j], 0) (row kernel only).
template <bool NEG, bool WRITE_ALIGN, bool WRITE_A1>
__device__ __forceinline__ void spmax_core(const float* __restrict__ xrow,
                                           float* __restrict__ align_row,
                                           float* __restrict__ a1_row,
                                           const float* __restrict__ tau_col,
                                           float* __restrict__ tau_store,
                                           const float* __restrict__ V,
                                           float* __restrict__ mix_out, int row) {
    __shared__ float red[8 + 64];
    __shared__ float s_p[CAPS];
    __shared__ unsigned short s_j[CAPS];
    int tid = threadIdx.x;   // 256

    float x[16];
    float vmax = -3.0e38f;
#pragma unroll
    for (int k = 0; k < 4; k++) {
        float4 v = *(const float4*)(xrow + tid * 4 + k * 1024);
        if (NEG) { v.x = -v.x; v.y = -v.y; v.z = -v.z; v.w = -v.w; }
        x[k * 4 + 0] = v.x; x[k * 4 + 1] = v.y;
        x[k * 4 + 2] = v.z; x[k * 4 + 3] = v.w;
        vmax = fmaxf(vmax, fmaxf(fmaxf(v.x, v.y), fmaxf(v.z, v.w)));
    }

    float m = warpRedMax(vmax);
    if ((tid & 31) == 0) red[tid >> 5] = m;
    __syncthreads();
    float bm = red[0];
#pragma unroll
    for (int i = 1; i < 8; i++) bm = fmaxf(bm, red[i]);

    float tau = bm - 1.0f;
    int kprev = -1;

    for (int it = 0; it < 64; ++it) {
        float ls = 0.f, lc = 0.f;
#pragma unroll
        for (int s = 0; s < 16; s++) {
            float v = x[s];
            if (v > tau) { ls += v; lc += 1.0f; }
        }
        ls = warpRedSum(ls);
        lc = warpRedSum(lc);
        int p = it & 1;
        float* buf = red + 8 + p * 32;
        if ((tid & 31) == 0) { buf[tid >> 5] = ls; buf[8 + (tid >> 5)] = lc; }
        __syncthreads();
        float S = 0.f, K = 0.f;
#pragma unroll
        for (int i = 0; i < 8; i++) { S += buf[i]; K += buf[8 + i]; }
        int k = (int)K;
        if (k == kprev) break;
        tau = (S - 1.0f) / K;
        kprev = k;
    }

    if (tau_store && tid == 0) *tau_store = tau;

    if (WRITE_ALIGN) {
#pragma unroll
        for (int k = 0; k < 4; k++) {
            int j = tid * 4 + k * 1024;
            float4 o;
            o.x = fmaxf(x[k * 4 + 0] - tau, 0.f);
            o.y = fmaxf(x[k * 4 + 1] - tau, 0.f);
            o.z = fmaxf(x[k * 4 + 2] - tau, 0.f);
            o.w = fmaxf(x[k * 4 + 3] - tau, 0.f);
            __stcs((float4*)(align_row + j), o);
            if (WRITE_A1) {
                const float4 tc = *(const float4*)(tau_col + j);
                float4 o1;
                o1.x = fmaxf(x[k * 4 + 0] - tc.x, 0.f);
                o1.y = fmaxf(x[k * 4 + 1] - tc.y, 0.f);
                o1.z = fmaxf(x[k * 4 + 2] - tc.z, 0.f);
                o1.w = fmaxf(x[k * 4 + 3] - tc.w, 0.f);
                __stcs((float4*)(a1_row + j), o1);
            }
        }
    }

    int cnt = 0;
#pragma unroll
    for (int s = 0; s < 16; s++)
        if (x[s] > tau) cnt++;
    int nnz;
    int base = blockScanExcl(cnt, nnz, tid);
    if (nnz <= CAPS) {
        int pos = base;
#pragma unroll
        for (int s = 0; s < 16; s++) {
            if (x[s] > tau) {
                s_p[pos] = x[s] - tau;
                s_j[pos] = (unsigned short)(tid * 4 + (s >> 2) * 1024 + (s & 3));
                pos++;
            }
        }
    }
    __syncthreads();

    float acc = 0.f;
    if (nnz <= CAPS) {
#pragma unroll 4
        for (int n = 0; n < nnz; n++)
            acc = fmaf(s_p[n], V[(size_t)s_j[n] * DD + tid], acc);
    } else {
        for (int j = 0; j < NN; j++) {
            float xv = NEG ? -xrow[j] : xrow[j];
            float p = xv - tau;
            if (p > 0.f) acc = fmaf(p, V[(size_t)j * DD + tid], acc);
        }
    }
    mix_out[(size_t)row * DD + tid] = acc;
}

// ---------------- kernels ----------------
__global__ void zero_kernel() {
    int t = threadIdx.x;
    g_v1[t] = 0.f;
    g_v2[t] = 0.f;
}

// float4 both directions; 32x32 tile, 256 threads (8x32)
__global__ void transpose_neg_kernel(const float* __restrict__ in) {
    __shared__ float s[32][33];
    int bx = blockIdx.x * 32, by = blockIdx.y * 32;
    int tx = threadIdx.x;   // 0..7
    int ty = threadIdx.y;   // 0..31

    float4 v = *(const float4*)(in + (size_t)(by + ty) * NN + bx + tx * 4);
    s[ty][tx * 4 + 0] = -v.x;
    s[ty][tx * 4 + 1] = -v.y;
    s[ty][tx * 4 + 2] = -v.z;
    s[ty][tx * 4 + 3] = -v.w;
    __syncthreads();

    float4 o;
    o.x = s[tx * 4 + 0][ty];
    o.y = s[tx * 4 + 1][ty];
    o.z = s[tx * 4 + 2][ty];
    o.w = s[tx * 4 + 3][ty];
    *(float4*)(g_negT + (size_t)(bx + ty) * NN + by + tx * 4) = o;
}

__global__ __launch_bounds__(256) void spmax_col_kernel(const float* __restrict__ rowvecs) {
    int row = blockIdx.x;   // column index of the original cost matrix
    spmax_core<false, false, false>(g_negT + (size_t)row * NN, nullptr, nullptr, nullptr,
                                    &g_tau_col[row], rowvecs, g_alpha, row);
}

__global__ __launch_bounds__(256) void spmax_row_kernel(const float* __restrict__ cost,
                                                        float* __restrict__ a0,
                                                        float* __restrict__ a1,
                                                        const float* __restrict__ colvecs) {
    int row = blockIdx.x;
    spmax_core<true, true, true>(cost + (size_t)row * NN, a0 + (size_t)row * NN,
                                 a1 + (size_t)row * NN, g_tau_col, nullptr,
                                 colvecs, g_beta, row);
}

// leaky_relu(X @ W + b) partial means — packed f32x2 FMA (Blackwell FFMA2 pipe).
// 16 rows/block as 8 row-pairs packed into 64-bit smem words; thread = out column.
__global__ __launch_bounds__(256) void g_mean_kernel(const float* __restrict__ Wg,
                                                     const float* __restrict__ bg,
                                                     int which) {
    const float* Xall = which ? g_alpha : g_beta;
    float* gv = which ? g_v2 : g_v1;
    __shared__ unsigned long long xs2[8 * 256];   // [pair][k] = pack(x[2i][k], x[2i+1][k])
    int tid = threadIdx.x;
    size_t r0 = (size_t)blockIdx.x * 16;

#pragma unroll
    for (int i = 0; i < 8; i++) {
        float a = Xall[(r0 + 2 * i) * 256 + tid];
        float b = Xall[(r0 + 2 * i + 1) * 256 + tid];
        unsigned long long p;
        asm("mov.b64 %0, {%1, %2};" : "=l"(p) : "f"(a), "f"(b));
        xs2[i * 256 + tid] = p;
    }
    __syncthreads();

    unsigned long long acc[8];
#pragma unroll
    for (int i = 0; i < 8; i++) acc[i] = 0ull;   // (0.0f, 0.0f)

#pragma unroll 2
    for (int k = 0; k < 256; k += 4) {
        float w0 = Wg[(k + 0) * 256 + tid];
        float w1 = Wg[(k + 1) * 256 + tid];
        float w2 = Wg[(k + 2) * 256 + tid];
        float w3 = Wg[(k + 3) * 256 + tid];
        unsigned long long wd0, wd1, wd2, wd3;
        asm("mov.b64 %0, {%1, %1};" : "=l"(wd0) : "f"(w0));
        asm("mov.b64 %0, {%1, %1};" : "=l"(wd1) : "f"(w1));
        asm("mov.b64 %0, {%1, %1};" : "=l"(wd2) : "f"(w2));
        asm("mov.b64 %0, {%1, %1};" : "=l"(wd3) : "f"(w3));
#pragma unroll
        for (int i = 0; i < 8; i++) {
            unsigned long long xv0 = xs2[i * 256 + k + 0];
            unsigned long long xv1 = xs2[i * 256 + k + 1];
            unsigned long long xv2 = xs2[i * 256 + k + 2];
            unsigned long long xv3 = xs2[i * 256 + k + 3];
            asm("fma.rn.f32x2 %0, %1, %2, %0;" : "+l"(acc[i]) : "l"(xv0), "l"(wd0));
            asm("fma.rn.f32x2 %0, %1, %2, %0;" : "+l"(acc[i]) : "l"(xv1), "l"(wd1));
            asm("fma.rn.f32x2 %0, %1, %2, %0;" : "+l"(acc[i]) : "l"(xv2), "l"(wd2));
            asm("fma.rn.f32x2 %0, %1, %2, %0;" : "+l"(acc[i]) : "l"(xv3), "l"(wd3));
        }
    }

    float bb = bg[tid], s = 0.f;
#pragma unroll
    for (int i = 0; i < 8; i++) {
        float lo, hi;
        asm("mov.b64 {%0, %1}, %2;" : "=f"(lo), "=f"(hi) : "l"(acc[i]));
        float z0 = lo + bb, z1 = hi + bb;
        s += (z0 > 0.f) ? z0 : 0.2f * z0;
        s += (z1 > 0.f) ? z1 : 0.2f * z1;
    }
    atomicAdd(&gv[tid], s);
}

__global__ void cosine_kernel() {
    __shared__ float red[24];
    int tid = threadIdx.x;
    float v1 = g_v1[tid] * (1.0f / NN);
    float v2 = g_v2[tid] * (1.0f / NN);
    float d = v1 * v2, a = v1 * v1, b = v2 * v2;
    d = warpRedSum(d); a = warpRedSum(a); b = warpRedSum(b);
    if ((tid & 31) == 0) {
        red[tid >> 5] = d; red[8 + (tid >> 5)] = a; red[16 + (tid >> 5)] = b;
    }
    __syncthreads();
    if (tid == 0) {
        float D = 0.f, A = 0.f, B = 0.f;
#pragma unroll
        for (int i = 0; i < 8; i++) { D += red[i]; A += red[8 + i]; B += red[16 + i]; }
        g_y = 1.0f - D / (sqrtf(A) * sqrtf(B) + 1e-8f);
    }
}

__global__ void fill_kernel(float* __restrict__ out) {
    float y = g_y;
    size_t idx = ((size_t)blockIdx.x * blockDim.x + threadIdx.x) * 4;
    __stcs((float4*)(out + idx), make_float4(y, y, y, y));
}

// ---------------- launch ----------------
extern "C" void kernel_launch(void* const* d_in, const int* in_sizes, int n_in,
                              void* d_out, int out_size) {
    const float* row_vecs    = (const float*)d_in[0];
    const float* column_vecs = (const float*)d_in[1];
    const float* cost        = (const float*)d_in[2];
    const float* W_G         = (const float*)d_in[3];
    const float* b_G         = (const float*)d_in[4];

    float* out      = (float*)d_out;
    float* cost_out = out;
    float* a0       = out + (size_t)NN * NN;
    float* a1       = out + 2 * (size_t)NN * NN;

    (void)in_sizes; (void)n_in; (void)out_size;

    zero_kernel<<<1, 256>>>();
    transpose_neg_kernel<<<dim3(NN / 32, NN / 32), dim3(8, 32)>>>(cost);
    spmax_col_kernel<<<NN, 256>>>(row_vecs);                  // tau_col + alpha
    g_mean_kernel<<<NN / 16, 256>>>(W_G, b_G, 1);             // v2 from alpha
    spmax_row_kernel<<<NN, 256>>>(cost, a0, a1, column_vecs); // a0, a1, beta
    g_mean_kernel<<<NN / 16, 256>>>(W_G, b_G, 0);             // v1 from beta
    cosine_kernel<<<1, 256>>>();
    fill_kernel<<<(NN * (size_t)NN) / (4 * 256), 256>>>(cost_out);
}

// round 7
// speedup vs baseline: 1.4182x; 1.1801x over previous
#include <cuda_runtime.h>
#include <math.h>

#define NN 4096
#define DD 256
#define CAPS 1024   // support/candidate capacity (expected nnz ~ 5-10)

// ---------------- device scratch ----------------
__device__ float g_negT[(size_t)NN * NN];   // -cost^T
__device__ float g_tau_col[NN];
__device__ float g_beta[(size_t)NN * DD];
__device__ float g_alpha[(size_t)NN * DD];
__device__ float g_v1[DD];
__device__ float g_v2[DD];
__device__ float g_y;

// ---------------- warp helpers ----------------
__device__ __forceinline__ float warpRedSum(float v) {
#pragma unroll
    for (int o = 16; o > 0; o >>= 1) v += __shfl_xor_sync(0xffffffffu, v, o);
    return v;
}
__device__ __forceinline__ float warpRedMax(float v) {
#pragma unroll
    for (int o = 16; o > 0; o >>= 1) v = fmaxf(v, __shfl_xor_sync(0xffffffffu, v, o));
    return v;
}

// exclusive scan of per-thread counts over 256 threads
__device__ __forceinline__ int blockScanExcl(int cnt, int& total, int tid) {
    __shared__ int warp_tot[8];
    const unsigned mask = 0xffffffffu;
    int lane = tid & 31, w = tid >> 5;
    int incl = cnt;
#pragma unroll
    for (int o = 1; o < 32; o <<= 1) {
        int n = __shfl_up_sync(mask, incl, o);
        if (lane >= o) incl += n;
    }
    if (lane == 31) warp_tot[w] = incl;
    __syncthreads();
    if (w == 0) {
        int t = (lane < 8) ? warp_tot[lane] : 0;
#pragma unroll
        for (int o = 1; o < 8; o <<= 1) {
            int n = __shfl_up_sync(mask, t, o);
            if (lane >= o) t += n;
        }
        if (lane < 8) warp_tot[lane] = t;
    }
    __syncthreads();
    int warp_off = (w == 0) ? 0 : warp_tot[w - 1];
    total = warp_tot[7];
    __syncthreads();
    return warp_off + incl - cnt;
}

// ---------------- register-resident sparsemax core ----------------
template <bool NEG, bool WRITE_ALIGN, bool WRITE_A1>
__device__ __forceinline__ void spmax_core(const float* __restrict__ xrow,
                                           float* __restrict__ align_row,
                                           float* __restrict__ a1_row,
                                           const float* __restrict__ tau_col,
                                           float* __restrict__ tau_store,
                                           const float* __restrict__ V,
                                           float* __restrict__ mix_out, int row) {
    __shared__ float red[8 + 64];
    __shared__ float s_p[CAPS];
    __shared__ unsigned short s_j[CAPS];
    int tid = threadIdx.x;   // 256

    float x[16];
    float vmax = -3.0e38f;
#pragma unroll
    for (int k = 0; k < 4; k++) {
        float4 v = *(const float4*)(xrow + tid * 4 + k * 1024);
        if (NEG) { v.x = -v.x; v.y = -v.y; v.z = -v.z; v.w = -v.w; }
        x[k * 4 + 0] = v.x; x[k * 4 + 1] = v.y;
        x[k * 4 + 2] = v.z; x[k * 4 + 3] = v.w;
        vmax = fmaxf(vmax, fmaxf(fmaxf(v.x, v.y), fmaxf(v.z, v.w)));
    }

    float m = warpRedMax(vmax);
    if ((tid & 31) == 0) red[tid >> 5] = m;
    __syncthreads();
    float bm = red[0];
#pragma unroll
    for (int i = 1; i < 8; i++) bm = fmaxf(bm, red[i]);

    float tau = bm - 1.0f;
    int kprev = -1;

    for (int it = 0; it < 64; ++it) {
        float ls = 0.f, lc = 0.f;
#pragma unroll
        for (int s = 0; s < 16; s++) {
            float v = x[s];
            if (v > tau) { ls += v; lc += 1.0f; }
        }
        ls = warpRedSum(ls);
        lc = warpRedSum(lc);
        int p = it & 1;
        float* buf = red + 8 + p * 32;
        if ((tid & 31) == 0) { buf[tid >> 5] = ls; buf[8 + (tid >> 5)] = lc; }
        __syncthreads();
        float S = 0.f, K = 0.f;
#pragma unroll
        for (int i = 0; i < 8; i++) { S += buf[i]; K += buf[8 + i]; }
        int k = (int)K;
        if (k == kprev) break;
        tau = (S - 1.0f) / K;
        kprev = k;
    }

    if (tau_store && tid == 0) *tau_store = tau;

    if (WRITE_ALIGN) {
#pragma unroll
        for (int k = 0; k < 4; k++) {
            int j = tid * 4 + k * 1024;
            float4 o;
            o.x = fmaxf(x[k * 4 + 0] - tau, 0.f);
            o.y = fmaxf(x[k * 4 + 1] - tau, 0.f);
            o.z = fmaxf(x[k * 4 + 2] - tau, 0.f);
            o.w = fmaxf(x[k * 4 + 3] - tau, 0.f);
            __stcs((float4*)(align_row + j), o);
            if (WRITE_A1) {
                const float4 tc = *(const float4*)(tau_col + j);
                float4 o1;
                o1.x = fmaxf(x[k * 4 + 0] - tc.x, 0.f);
                o1.y = fmaxf(x[k * 4 + 1] - tc.y, 0.f);
                o1.z = fmaxf(x[k * 4 + 2] - tc.z, 0.f);
                o1.w = fmaxf(x[k * 4 + 3] - tc.w, 0.f);
                __stcs((float4*)(a1_row + j), o1);
            }
        }
    }

    int cnt = 0;
#pragma unroll
    for (int s = 0; s < 16; s++)
        if (x[s] > tau) cnt++;
    int nnz;
    int base = blockScanExcl(cnt, nnz, tid);
    if (nnz <= CAPS) {
        int pos = base;
#pragma unroll
        for (int s = 0; s < 16; s++) {
            if (x[s] > tau) {
                s_p[pos] = x[s] - tau;
                s_j[pos] = (unsigned short)(tid * 4 + (s >> 2) * 1024 + (s & 3));
                pos++;
            }
        }
    }
    __syncthreads();

    float acc = 0.f;
    if (nnz <= CAPS) {
#pragma unroll 4
        for (int n = 0; n < nnz; n++)
            acc = fmaf(s_p[n], V[(size_t)s_j[n] * DD + tid], acc);
    } else {
        for (int j = 0; j < NN; j++) {
            float xv = NEG ? -xrow[j] : xrow[j];
            float p = xv - tau;
            if (p > 0.f) acc = fmaf(p, V[(size_t)j * DD + tid], acc);
        }
    }
    mix_out[(size_t)row * DD + tid] = acc;
}

// ---------------- kernels ----------------
__global__ void zero_kernel() {
    int t = threadIdx.x;
    g_v1[t] = 0.f;
    g_v2[t] = 0.f;
}

__global__ void transpose_neg_kernel(const float* __restrict__ in) {
    __shared__ float s[32][33];
    int bx = blockIdx.x * 32, by = blockIdx.y * 32;
    int tx = threadIdx.x;   // 0..7
    int ty = threadIdx.y;   // 0..31

    float4 v = *(const float4*)(in + (size_t)(by + ty) * NN + bx + tx * 4);
    s[ty][tx * 4 + 0] = -v.x;
    s[ty][tx * 4 + 1] = -v.y;
    s[ty][tx * 4 + 2] = -v.z;
    s[ty][tx * 4 + 3] = -v.w;
    __syncthreads();

    float4 o;
    o.x = s[tx * 4 + 0][ty];
    o.y = s[tx * 4 + 1][ty];
    o.z = s[tx * 4 + 2][ty];
    o.w = s[tx * 4 + 3][ty];
    *(float4*)(g_negT + (size_t)(bx + ty) * NN + by + tx * 4) = o;
}

__global__ __launch_bounds__(256) void spmax_col_kernel(const float* __restrict__ rowvecs) {
    int row = blockIdx.x;   // column index of the original cost matrix
    spmax_core<false, false, false>(g_negT + (size_t)row * NN, nullptr, nullptr, nullptr,
                                    &g_tau_col[row], rowvecs, g_alpha, row);
}

__global__ __launch_bounds__(256) void spmax_row_kernel(const float* __restrict__ cost,
                                                        float* __restrict__ a0,
                                                        float* __restrict__ a1,
                                                        const float* __restrict__ colvecs) {
    int row = blockIdx.x;
    spmax_core<true, true, true>(cost + (size_t)row * NN, a0 + (size_t)row * NN,
                                 a1 + (size_t)row * NN, g_tau_col, nullptr,
                                 colvecs, g_beta, row);
}

// leaky_relu(X @ W + b) partial means — packed f32x2 FMA.
// grid (256, 2): y selects alpha/beta. 16 rows/block as 8 packed pairs.
// k unrolled by 8 with batched Wg prefetch (MLP 8); xs2 read as 128-bit pairs.
__global__ __launch_bounds__(256) void g_mean_kernel(const float* __restrict__ Wg,
                                                     const float* __restrict__ bg) {
    int which = blockIdx.y;
    const float* Xall = which ? g_alpha : g_beta;
    float* gv = which ? g_v2 : g_v1;
    __shared__ unsigned long long xs2[8 * 256];   // [pair][k]
    int tid = threadIdx.x;
    size_t r0 = (size_t)blockIdx.x * 16;

#pragma unroll
    for (int i = 0; i < 8; i++) {
        float a = Xall[(r0 + 2 * i) * 256 + tid];
        float b = Xall[(r0 + 2 * i + 1) * 256 + tid];
        unsigned long long p;
        asm("mov.b64 %0, {%1, %2};" : "=l"(p) : "f"(a), "f"(b));
        xs2[i * 256 + tid] = p;
    }
    __syncthreads();

    unsigned long long acc[8];
#pragma unroll
    for (int i = 0; i < 8; i++) acc[i] = 0ull;

    for (int k0 = 0; k0 < 256; k0 += 8) {
        // batched prefetch of 8 W values (8 outstanding LDGs)
        float w[8];
#pragma unroll
        for (int u = 0; u < 8; u++) w[u] = Wg[(size_t)(k0 + u) * 256 + tid];

#pragma unroll
        for (int u = 0; u < 8; u += 2) {
            unsigned long long wd0, wd1;
            asm("mov.b64 %0, {%1, %1};" : "=l"(wd0) : "f"(w[u]));
            asm("mov.b64 %0, {%1, %1};" : "=l"(wd1) : "f"(w[u + 1]));
#pragma unroll
            for (int i = 0; i < 8; i++) {
                ulonglong2 xv = *(const ulonglong2*)&xs2[i * 256 + k0 + u];
                asm("fma.rn.f32x2 %0, %1, %2, %0;" : "+l"(acc[i]) : "l"(xv.x), "l"(wd0));
                asm("fma.rn.f32x2 %0, %1, %2, %0;" : "+l"(acc[i]) : "l"(xv.y), "l"(wd1));
            }
        }
    }

    float bb = bg[tid], s = 0.f;
#pragma unroll
    for (int i = 0; i < 8; i++) {
        float lo, hi;
        asm("mov.b64 {%0, %1}, %2;" : "=f"(lo), "=f"(hi) : "l"(acc[i]));
        float z0 = lo + bb, z1 = hi + bb;
        s += (z0 > 0.f) ? z0 : 0.2f * z0;
        s += (z1 > 0.f) ? z1 : 0.2f * z1;
    }
    atomicAdd(&gv[tid], s);
}

__global__ void cosine_kernel() {
    __shared__ float red[24];
    int tid = threadIdx.x;
    float v1 = g_v1[tid] * (1.0f / NN);
    float v2 = g_v2[tid] * (1.0f / NN);
    float d = v1 * v2, a = v1 * v1, b = v2 * v2;
    d = warpRedSum(d); a = warpRedSum(a); b = warpRedSum(b);
    if ((tid & 31) == 0) {
        red[tid >> 5] = d; red[8 + (tid >> 5)] = a; red[16 + (tid >> 5)] = b;
    }
    __syncthreads();
    if (tid == 0) {
        float D = 0.f, A = 0.f, B = 0.f;
#pragma unroll
        for (int i = 0; i < 8; i++) { D += red[i]; A += red[8 + i]; B += red[16 + i]; }
        g_y = 1.0f - D / (sqrtf(A) * sqrtf(B) + 1e-8f);
    }
}

__global__ void fill_kernel(float* __restrict__ out) {
    float y = g_y;
    size_t idx = ((size_t)blockIdx.x * blockDim.x + threadIdx.x) * 4;
    __stcs((float4*)(out + idx), make_float4(y, y, y, y));
}

// ---------------- launch ----------------
extern "C" void kernel_launch(void* const* d_in, const int* in_sizes, int n_in,
                              void* d_out, int out_size) {
    const float* row_vecs    = (const float*)d_in[0];
    const float* column_vecs = (const float*)d_in[1];
    const float* cost        = (const float*)d_in[2];
    const float* W_G         = (const float*)d_in[3];
    const float* b_G         = (const float*)d_in[4];

    float* out      = (float*)d_out;
    float* cost_out = out;
    float* a0       = out + (size_t)NN * NN;
    float* a1       = out + 2 * (size_t)NN * NN;

    (void)in_sizes; (void)n_in; (void)out_size;

    zero_kernel<<<1, 256>>>();
    transpose_neg_kernel<<<dim3(NN / 32, NN / 32), dim3(8, 32)>>>(cost);
    spmax_col_kernel<<<NN, 256>>>(row_vecs);                   // tau_col + alpha
    spmax_row_kernel<<<NN, 256>>>(cost, a0, a1, column_vecs);  // a0, a1, beta
    g_mean_kernel<<<dim3(NN / 16, 2), 256>>>(W_G, b_G);        // v1 & v2 in one wave
    cosine_kernel<<<1, 256>>>();
    fill_kernel<<<(NN * (size_t)NN) / (4 * 256), 256>>>(cost_out);
}

// round 8
// speedup vs baseline: 1.4715x; 1.0375x over previous
#include <cuda_runtime.h>
#include <math.h>

#define NN 4096
#define DD 256
#define CAPS 1024     // row support capacity (smem, typical nnz ~ 6)
#define CCAP 1024     // per-column candidate capacity (global, typical ~8)

// ---------------- device scratch ----------------
__device__ unsigned g_colmax_enc[NN];                 // encoded col max of -cost
__device__ int      g_colcnt[NN];
__device__ float    g_colval[(size_t)NN * CCAP];
__device__ unsigned short g_colrow[(size_t)NN * CCAP];
__device__ float g_tau_col[NN];
__device__ float g_beta[(size_t)NN * DD];
__device__ float g_alpha[(size_t)NN * DD];
__device__ float g_v1[DD];
__device__ float g_v2[DD];
__device__ float g_y;

// monotonic float<->unsigned encoding for atomicMax
__device__ __forceinline__ unsigned encf(float f) {
    unsigned i = __float_as_uint(f);
    return (i & 0x80000000u) ? ~i : (i | 0x80000000u);
}
__device__ __forceinline__ float decf(unsigned u) {
    return (u & 0x80000000u) ? __uint_as_float(u & 0x7fffffffu) : __uint_as_float(~u);
}

// ---------------- warp helpers ----------------
__device__ __forceinline__ float warpRedSum(float v) {
#pragma unroll
    for (int o = 16; o > 0; o >>= 1) v += __shfl_xor_sync(0xffffffffu, v, o);
    return v;
}
__device__ __forceinline__ float warpRedMax(float v) {
#pragma unroll
    for (int o = 16; o > 0; o >>= 1) v = fmaxf(v, __shfl_xor_sync(0xffffffffu, v, o));
    return v;
}

__device__ __forceinline__ int blockScanExcl(int cnt, int& total, int tid) {
    __shared__ int warp_tot[8];
    const unsigned mask = 0xffffffffu;
    int lane = tid & 31, w = tid >> 5;
    int incl = cnt;
#pragma unroll
    for (int o = 1; o < 32; o <<= 1) {
        int n = __shfl_up_sync(mask, incl, o);
        if (lane >= o) incl += n;
    }
    if (lane == 31) warp_tot[w] = incl;
    __syncthreads();
    if (w == 0) {
        int t = (lane < 8) ? warp_tot[lane] : 0;
#pragma unroll
        for (int o = 1; o < 8; o <<= 1) {
            int n = __shfl_up_sync(mask, t, o);
            if (lane >= o) t += n;
        }
        if (lane < 8) warp_tot[lane] = t;
    }
    __syncthreads();
    int warp_off = (w == 0) ? 0 : warp_tot[w - 1];
    total = warp_tot[7];
    __syncthreads();
    return warp_off + incl - cnt;
}

// ---------------- kernels ----------------
__global__ void zero_kernel() {
    int t = blockIdx.x * 256 + threadIdx.x;   // grid 16 -> 4096 threads
    g_colcnt[t] = 0;
    g_colmax_enc[t] = 0u;                     // < enc of any real float
    if (t < DD) { g_v1[t] = 0.f; g_v2[t] = 0.f; }
}

// per-column max of -cost: 64-row x 256-col tiles, one atomicMax per (block, col)
__global__ __launch_bounds__(256) void colmax_kernel(const float* __restrict__ cost) {
    int c = blockIdx.x * 256 + threadIdx.x;
    size_t r0 = (size_t)blockIdx.y * 64;
    float m = -3.0e38f;
#pragma unroll 8
    for (int r = 0; r < 64; r++)
        m = fmaxf(m, -cost[(r0 + r) * NN + c]);
    atomicMax(&g_colmax_enc[c], encf(m));
}

// row sparsemax (register-resident Michelot) + a0 + beta mix + column-candidate harvest
__global__ __launch_bounds__(256) void spmax_row_kernel(const float* __restrict__ cost,
                                                        float* __restrict__ a0,
                                                        const float* __restrict__ colvecs) {
    __shared__ float red[8 + 64];
    __shared__ float s_p[CAPS];
    __shared__ unsigned short s_j[CAPS];
    int tid = threadIdx.x;   // 256
    int row = blockIdx.x;
    const float* xrow = cost + (size_t)row * NN;

    float x[16];
    float vmax = -3.0e38f;
#pragma unroll
    for (int k = 0; k < 4; k++) {
        float4 v = *(const float4*)(xrow + tid * 4 + k * 1024);
        x[k * 4 + 0] = -v.x; x[k * 4 + 1] = -v.y;
        x[k * 4 + 2] = -v.z; x[k * 4 + 3] = -v.w;
        vmax = fmaxf(vmax, fmaxf(fmaxf(-v.x, -v.y), fmaxf(-v.z, -v.w)));
    }

    float m = warpRedMax(vmax);
    if ((tid & 31) == 0) red[tid >> 5] = m;
    __syncthreads();
    float bm = red[0];
#pragma unroll
    for (int i = 1; i < 8; i++) bm = fmaxf(bm, red[i]);

    float tau = bm - 1.0f;   // tau0 <= tau*: Michelot-valid start
    int kprev = -1;
    for (int it = 0; it < 64; ++it) {
        float ls = 0.f, lc = 0.f;
#pragma unroll
        for (int s = 0; s < 16; s++) {
            float v = x[s];
            if (v > tau) { ls += v; lc += 1.0f; }
        }
        ls = warpRedSum(ls);
        lc = warpRedSum(lc);
        int p = it & 1;
        float* buf = red + 8 + p * 32;
        if ((tid & 31) == 0) { buf[tid >> 5] = ls; buf[8 + (tid >> 5)] = lc; }
        __syncthreads();
        float S = 0.f, K = 0.f;
#pragma unroll
        for (int i = 0; i < 8; i++) { S += buf[i]; K += buf[8 + i]; }
        int k = (int)K;
        if (k == kprev) break;
        tau = (S - 1.0f) / K;
        kprev = k;
    }

    // a0 from registers + column candidate harvest (x > colmax[j]-1)
#pragma unroll
    for (int k = 0; k < 4; k++) {
        int j = tid * 4 + k * 1024;
        float4 o;
        o.x = fmaxf(x[k * 4 + 0] - tau, 0.f);
        o.y = fmaxf(x[k * 4 + 1] - tau, 0.f);
        o.z = fmaxf(x[k * 4 + 2] - tau, 0.f);
        o.w = fmaxf(x[k * 4 + 3] - tau, 0.f);
        __stcs((float4*)(a0 + (size_t)row * NN + j), o);

        uint4 cm = *(const uint4*)(g_colmax_enc + j);
#pragma unroll
        for (int c = 0; c < 4; c++) {
            float xv = x[k * 4 + c];
            unsigned ce = (c == 0) ? cm.x : (c == 1) ? cm.y : (c == 2) ? cm.z : cm.w;
            if (xv > decf(ce) - 1.0f) {
                int jj = j + c;
                int pos = atomicAdd(&g_colcnt[jj], 1);
                if (pos < CCAP) {
                    g_colval[(size_t)jj * CCAP + pos] = xv;
                    g_colrow[(size_t)jj * CCAP + pos] = (unsigned short)row;
                }
            }
        }
    }

    // row support compaction + beta mix
    int cnt = 0;
#pragma unroll
    for (int s = 0; s < 16; s++)
        if (x[s] > tau) cnt++;
    int nnz;
    int base = blockScanExcl(cnt, nnz, tid);
    if (nnz <= CAPS) {
        int pos = base;
#pragma unroll
        for (int s = 0; s < 16; s++) {
            if (x[s] > tau) {
                s_p[pos] = x[s] - tau;
                s_j[pos] = (unsigned short)(tid * 4 + (s >> 2) * 1024 + (s & 3));
                pos++;
            }
        }
    }
    __syncthreads();

    float acc = 0.f;
    if (nnz <= CAPS) {
#pragma unroll 4
        for (int n = 0; n < nnz; n++)
            acc = fmaf(s_p[n], colvecs[(size_t)s_j[n] * DD + tid], acc);
    } else {
        for (int j = 0; j < NN; j++) {
            float p = -xrow[j] - tau;
            if (p > 0.f) acc = fmaf(p, colvecs[(size_t)j * DD + tid], acc);
        }
    }
    g_beta[(size_t)row * DD + tid] = acc;
}

// per-column: exact Michelot on candidate list -> tau_col + alpha[j,:]
__global__ __launch_bounds__(256) void col_alpha_kernel(const float* __restrict__ cost,
                                                        const float* __restrict__ rowvecs) {
    __shared__ float sv[CCAP];
    __shared__ unsigned short si[CCAP];
    __shared__ float s_tau;
    int j = blockIdx.x;
    int tid = threadIdx.x, lane = tid & 31;
    int cnt = g_colcnt[j];

    if (cnt <= CCAP) {
        for (int n = tid; n < cnt; n += 256) {
            sv[n] = g_colval[(size_t)j * CCAP + n];
            si[n] = g_colrow[(size_t)j * CCAP + n];
        }
        __syncthreads();
        if (tid < 32) {
            float ls = 0.f;
            for (int n = lane; n < cnt; n += 32) ls += sv[n];
            ls = warpRedSum(ls);
            float t = (ls - 1.0f) / (float)cnt;   // Michelot start: full list
            int kprev = cnt;
            for (int it = 0; it < 48; ++it) {
                float s = 0.f, c = 0.f;
                for (int n = lane; n < cnt; n += 32) {
                    float v = sv[n];
                    if (v > t) { s += v; c += 1.0f; }
                }
                s = warpRedSum(s);
                c = warpRedSum(c);
                int k = (int)c;
                if (k == kprev) break;
                t = (s - 1.0f) / c;
                kprev = k;
            }
            if (lane == 0) s_tau = t;
        }
        __syncthreads();
        float tau = s_tau;
        if (tid == 0) g_tau_col[j] = tau;
        float acc = 0.f;
        for (int n = 0; n < cnt; n++) {
            float p = sv[n] - tau;
            if (p > 0.f) acc = fmaf(p, rowvecs[(size_t)si[n] * DD + tid], acc);
        }
        g_alpha[(size_t)j * DD + tid] = acc;
    } else {
        // dense fallback (never expected): warp Michelot over the raw column
        if (tid < 32) {
            float t = decf(g_colmax_enc[j]) - 1.0f;
            int kprev = -1;
            for (int it = 0; it < 64; ++it) {
                float s = 0.f, c = 0.f;
                for (int r = lane; r < NN; r += 32) {
                    float v = -cost[(size_t)r * NN + j];
                    if (v > t) { s += v; c += 1.0f; }
                }
                s = warpRedSum(s);
                c = warpRedSum(c);
                int k = (int)c;
                if (k == kprev) break;
                t = (s - 1.0f) / c;
                kprev = k;
            }
            if (lane == 0) s_tau = t;
        }
        __syncthreads();
        float tau = s_tau;
        if (tid == 0) g_tau_col[j] = tau;
        float acc = 0.f;
        for (int r = 0; r < NN; r++) {
            float p = -cost[(size_t)r * NN + j] - tau;
            if (p > 0.f) acc = fmaf(p, rowvecs[(size_t)r * DD + tid], acc);
        }
        g_alpha[(size_t)j * DD + tid] = acc;
    }
}

// leaky_relu(X @ W + b) partial means — packed f32x2 FMA; grid (256, 2)
__global__ __launch_bounds__(256) void g_mean_kernel(const float* __restrict__ Wg,
                                                     const float* __restrict__ bg) {
    int which = blockIdx.y;
    const float* Xall = which ? g_alpha : g_beta;
    float* gv = which ? g_v2 : g_v1;
    __shared__ unsigned long long xs2[8 * 256];
    int tid = threadIdx.x;
    size_t r0 = (size_t)blockIdx.x * 16;

#pragma unroll
    for (int i = 0; i < 8; i++) {
        float a = Xall[(r0 + 2 * i) * 256 + tid];
        float b = Xall[(r0 + 2 * i + 1) * 256 + tid];
        unsigned long long p;
        asm("mov.b64 %0, {%1, %2};" : "=l"(p) : "f"(a), "f"(b));
        xs2[i * 256 + tid] = p;
    }
    __syncthreads();

    unsigned long long acc[8];
#pragma unroll
    for (int i = 0; i < 8; i++) acc[i] = 0ull;

    for (int k0 = 0; k0 < 256; k0 += 8) {
        float w[8];
#pragma unroll
        for (int u = 0; u < 8; u++) w[u] = Wg[(size_t)(k0 + u) * 256 + tid];
#pragma unroll
        for (int u = 0; u < 8; u += 2) {
            unsigned long long wd0, wd1;
            asm("mov.b64 %0, {%1, %1};" : "=l"(wd0) : "f"(w[u]));
            asm("mov.b64 %0, {%1, %1};" : "=l"(wd1) : "f"(w[u + 1]));
#pragma unroll
            for (int i = 0; i < 8; i++) {
                ulonglong2 xv = *(const ulonglong2*)&xs2[i * 256 + k0 + u];
                asm("fma.rn.f32x2 %0, %1, %2, %0;" : "+l"(acc[i]) : "l"(xv.x), "l"(wd0));
                asm("fma.rn.f32x2 %0, %1, %2, %0;" : "+l"(acc[i]) : "l"(xv.y), "l"(wd1));
            }
        }
    }

    float bb = bg[tid], s = 0.f;
#pragma unroll
    for (int i = 0; i < 8; i++) {
        float lo, hi;
        asm("mov.b64 {%0, %1}, %2;" : "=f"(lo), "=f"(hi) : "l"(acc[i]));
        float z0 = lo + bb, z1 = hi + bb;
        s += (z0 > 0.f) ? z0 : 0.2f * z0;
        s += (z1 > 0.f) ? z1 : 0.2f * z1;
    }
    atomicAdd(&gv[tid], s);
}

__global__ void cosine_kernel() {
    __shared__ float red[24];
    int tid = threadIdx.x;
    float v1 = g_v1[tid] * (1.0f / NN);
    float v2 = g_v2[tid] * (1.0f / NN);
    float d = v1 * v2, a = v1 * v1, b = v2 * v2;
    d = warpRedSum(d); a = warpRedSum(a); b = warpRedSum(b);
    if ((tid & 31) == 0) {
        red[tid >> 5] = d; red[8 + (tid >> 5)] = a; red[16 + (tid >> 5)] = b;
    }
    __syncthreads();
    if (tid == 0) {
        float D = 0.f, A = 0.f, B = 0.f;
#pragma unroll
        for (int i = 0; i < 8; i++) { D += red[i]; A += red[8 + i]; B += red[16 + i]; }
        g_y = 1.0f - D / (sqrtf(A) * sqrtf(B) + 1e-8f);
    }
}

// fused tail: a1[i,j] = max(-cost[i,j] - tau_col[j], 0)  AND  cost_out = y
__global__ void tail_kernel(const float* __restrict__ cost,
                            float* __restrict__ a1, float* __restrict__ cost_out) {
    size_t idx = ((size_t)blockIdx.x * blockDim.x + threadIdx.x) * 4;
    int j = (int)(idx & (NN - 1));
    float4 c = *(const float4*)(cost + idx);
    const float4 tc = *(const float4*)(g_tau_col + j);
    float4 o;
    o.x = fmaxf(-c.x - tc.x, 0.f);
    o.y = fmaxf(-c.y - tc.y, 0.f);
    o.z = fmaxf(-c.z - tc.z, 0.f);
    o.w = fmaxf(-c.w - tc.w, 0.f);
    __stcs((float4*)(a1 + idx), o);
    float y = g_y;
    __stcs((float4*)(cost_out + idx), make_float4(y, y, y, y));
}

// ---------------- launch ----------------
extern "C" void kernel_launch(void* const* d_in, const int* in_sizes, int n_in,
                              void* d_out, int out_size) {
    const float* row_vecs    = (const float*)d_in[0];
    const float* column_vecs = (const float*)d_in[1];
    const float* cost        = (const float*)d_in[2];
    const float* W_G         = (const float*)d_in[3];
    const float* b_G         = (const float*)d_in[4];

    float* out      = (float*)d_out;
    float* cost_out = out;
    float* a0       = out + (size_t)NN * NN;
    float* a1       = out + 2 * (size_t)NN * NN;

    (void)in_sizes; (void)n_in; (void)out_size;

    zero_kernel<<<16, 256>>>();
    colmax_kernel<<<dim3(NN / 256, NN / 64), 256>>>(cost);
    spmax_row_kernel<<<NN, 256>>>(cost, a0, column_vecs);   // a0, beta, col candidates
    col_alpha_kernel<<<NN, 256>>>(cost, row_vecs);          // tau_col, alpha
    g_mean_kernel<<<dim3(NN / 16, 2), 256>>>(W_G, b_G);     // v1 & v2
    cosine_kernel<<<1, 256>>>();
    tail_kernel<<<(NN * (size_t)NN) / (4 * 256), 256>>>(cost, a1, cost_out);
}